// round 2
// baseline (speedup 1.0000x reference)
#include <cuda_runtime.h>
#include <math.h>

#define BB 2
#define SS 2048
#define EE 2048
#define HH 16
#define DD 128
#define MROWS (BB*SS)   // 4096

// Scratch (device globals: allocation-free per harness rules)
__device__ float g_Q[MROWS*EE];   // [B*H, S, D]
__device__ float g_K[MROWS*EE];   // [B*H, S, D]
__device__ float g_V[MROWS*EE];   // [B*H, S, D]
__device__ float g_A[MROWS*EE];   // attention out, [B, S, E]

// ---------------------------------------------------------------------------
// Tiled fp32 GEMM: Y = X @ W + bias
// X: [4096, 2048] row-major, W: [2048, 2048] row-major (k-major rows)
// OUT_HEADMAJOR=1: write Y[((b*H+h)*S+s)*D+d]   (n = h*D+d, m = b*S+s)
// OUT_HEADMAJOR=0: write Y[m*E+n]
// BM=BN=128, BK=8, 256 threads, 8x8 per thread
// ---------------------------------------------------------------------------
template<int OUT_HEADMAJOR>
__global__ __launch_bounds__(256)
void gemm_kernel(const float* __restrict__ X, const float* __restrict__ W,
                 const float* __restrict__ bias, float* __restrict__ Y)
{
    __shared__ float As[8][128];
    __shared__ float Bs[8][128];

    const int tid = threadIdx.x;
    const int m0 = blockIdx.y * 128;
    const int n0 = blockIdx.x * 128;

    const int a_row  = tid >> 1;          // 0..127
    const int a_col4 = (tid & 1) * 4;     // 0 or 4
    const int b_row  = tid >> 5;          // 0..7
    const int b_col  = (tid & 31) * 4;    // 0..124

    const int ty = tid >> 4;              // 0..15
    const int tx = tid & 15;              // 0..15

    float c[8][8];
#pragma unroll
    for (int i = 0; i < 8; i++)
#pragma unroll
        for (int j = 0; j < 8; j++) c[i][j] = 0.f;

    for (int k0 = 0; k0 < EE; k0 += 8) {
        float4 av = *(const float4*)&X[(size_t)(m0 + a_row)*EE + k0 + a_col4];
        float4 bv = *(const float4*)&W[(size_t)(k0 + b_row)*EE + n0 + b_col];
        As[a_col4+0][a_row] = av.x;
        As[a_col4+1][a_row] = av.y;
        As[a_col4+2][a_row] = av.z;
        As[a_col4+3][a_row] = av.w;
        *(float4*)&Bs[b_row][b_col] = bv;
        __syncthreads();

#pragma unroll
        for (int k = 0; k < 8; k++) {
            float a[8], b[8];
            *(float4*)&a[0] = *(float4*)&As[k][ty*8];
            *(float4*)&a[4] = *(float4*)&As[k][ty*8+4];
            *(float4*)&b[0] = *(float4*)&Bs[k][tx*8];
            *(float4*)&b[4] = *(float4*)&Bs[k][tx*8+4];
#pragma unroll
            for (int i = 0; i < 8; i++)
#pragma unroll
                for (int j = 0; j < 8; j++)
                    c[i][j] += a[i]*b[j];
        }
        __syncthreads();
    }

    // Epilogue
#pragma unroll
    for (int i = 0; i < 8; i++) {
        const int m = m0 + ty*8 + i;
        const int bI = m >> 11;        // / S
        const int sI = m & (SS-1);
        if (OUT_HEADMAJOR) {
            // whole block column is one head: n0..n0+127 -> h = n0>>7 fixed
            const int h = n0 >> 7;
            float* dst = &Y[(((size_t)(bI*HH + h)*SS + sI)*DD) + tx*8];
#pragma unroll
            for (int j = 0; j < 8; j++)
                dst[j] = c[i][j] + bias[n0 + tx*8 + j];
        } else {
            float* dst = &Y[(size_t)m*EE + n0 + tx*8];
#pragma unroll
            for (int j = 0; j < 8; j++)
                dst[j] = c[i][j] + bias[n0 + tx*8 + j];
        }
    }
}

// ---------------------------------------------------------------------------
// Flash attention (fp32, online softmax).
// Q,K,V: [B*H, S, D] head-major. Output Aout: [B, S, E].
// Block: one (bh, 64-row q-tile). 256 threads.
// Score micro-tile per thread: 4 q-rows x 4 k-cols. PV: 4 q-rows x 8 d-cols.
// ---------------------------------------------------------------------------
#define QT 64
#define KT 64
#define LDQ 132   // padded row stride (floats) to avoid bank conflicts
#define ATTN_SMEM_FLOATS (QT*LDQ + KT*LDQ + QT*KT)
#define ATTN_SMEM_BYTES  (ATTN_SMEM_FLOATS * 4)

__global__ __launch_bounds__(256)
void attn_kernel(const float* __restrict__ Q, const float* __restrict__ K,
                 const float* __restrict__ V, float* __restrict__ Aout)
{
    extern __shared__ float sm[];
    float* Qs  = sm;                 // QT x LDQ
    float* KVs = sm + QT*LDQ;        // KT x LDQ  (K tile, then reused for V tile)
    float* Ps  = sm + QT*LDQ + KT*LDQ; // QT x KT

    const int tid = threadIdx.x;
    const int bh  = blockIdx.y;
    const int q0  = blockIdx.x * QT;

    const float* Qb = Q + (size_t)bh*SS*DD;
    const float* Kb = K + (size_t)bh*SS*DD;
    const float* Vb = V + (size_t)bh*SS*DD;

    // Load Q tile (64 x 128), padded stride
    for (int it = tid; it < QT*32; it += 256) {
        const int row = it >> 5;
        const int c4  = (it & 31) * 4;
        *(float4*)&Qs[row*LDQ + c4] = *(const float4*)&Qb[(size_t)(q0+row)*DD + c4];
    }

    const int rg = tid >> 4;     // 0..15
    const int cg = tid & 15;     // 0..15
    const int r0 = rg * 4;
    const int c0 = cg * 4;

    const float scale = 0.08838834764831845f; // 1/sqrt(128)

    float m_i[4], l_i[4], acc[4][8];
#pragma unroll
    for (int i = 0; i < 4; i++) {
        m_i[i] = -INFINITY; l_i[i] = 0.f;
#pragma unroll
        for (int j = 0; j < 8; j++) acc[i][j] = 0.f;
    }

    for (int kt = 0; kt < SS; kt += KT) {
        __syncthreads();   // prior PV done reading KVs/Ps
        // Load K tile
        for (int it = tid; it < KT*32; it += 256) {
            const int row = it >> 5;
            const int c4  = (it & 31) * 4;
            *(float4*)&KVs[row*LDQ + c4] = *(const float4*)&Kb[(size_t)(kt+row)*DD + c4];
        }
        __syncthreads();

        // Scores: s[4][4] = Q[r0..r0+3][:] . K[c0..c0+3][:]
        float s[4][4];
#pragma unroll
        for (int i = 0; i < 4; i++)
#pragma unroll
            for (int j = 0; j < 4; j++) s[i][j] = 0.f;

#pragma unroll 8
        for (int d = 0; d < DD; d += 4) {
            float4 qv[4], kv[4];
#pragma unroll
            for (int i = 0; i < 4; i++) qv[i] = *(float4*)&Qs[(r0+i)*LDQ + d];
#pragma unroll
            for (int j = 0; j < 4; j++) kv[j] = *(float4*)&KVs[(c0+j)*LDQ + d];
#pragma unroll
            for (int i = 0; i < 4; i++)
#pragma unroll
                for (int j = 0; j < 4; j++) {
                    s[i][j] += qv[i].x*kv[j].x;
                    s[i][j] += qv[i].y*kv[j].y;
                    s[i][j] += qv[i].z*kv[j].z;
                    s[i][j] += qv[i].w*kv[j].w;
                }
        }
#pragma unroll
        for (int i = 0; i < 4; i++)
#pragma unroll
            for (int j = 0; j < 4; j++) s[i][j] *= scale;

        // Row max across the 16 threads sharing this row group (lanes 0-15 / 16-31)
        float mnew[4];
#pragma unroll
        for (int i = 0; i < 4; i++) {
            float mx = fmaxf(fmaxf(s[i][0], s[i][1]), fmaxf(s[i][2], s[i][3]));
            mx = fmaxf(mx, __shfl_xor_sync(0xffffffffu, mx, 8));
            mx = fmaxf(mx, __shfl_xor_sync(0xffffffffu, mx, 4));
            mx = fmaxf(mx, __shfl_xor_sync(0xffffffffu, mx, 2));
            mx = fmaxf(mx, __shfl_xor_sync(0xffffffffu, mx, 1));
            mnew[i] = fmaxf(m_i[i], mx);
        }

        float p[4][4], rs[4];
#pragma unroll
        for (int i = 0; i < 4; i++) {
            const float alpha = __expf(m_i[i] - mnew[i]);
            m_i[i] = mnew[i];
            rs[i] = 0.f;
#pragma unroll
            for (int j = 0; j < 4; j++) {
                p[i][j] = __expf(s[i][j] - mnew[i]);
                rs[i] += p[i][j];
            }
            rs[i] += __shfl_xor_sync(0xffffffffu, rs[i], 8);
            rs[i] += __shfl_xor_sync(0xffffffffu, rs[i], 4);
            rs[i] += __shfl_xor_sync(0xffffffffu, rs[i], 2);
            rs[i] += __shfl_xor_sync(0xffffffffu, rs[i], 1);
            l_i[i] = l_i[i]*alpha + rs[i];
#pragma unroll
            for (int j = 0; j < 8; j++) acc[i][j] *= alpha;
        }

        // Stage P
#pragma unroll
        for (int i = 0; i < 4; i++)
#pragma unroll
            for (int j = 0; j < 4; j++)
                Ps[(r0+i)*KT + (c0+j)] = p[i][j];

        __syncthreads();   // K reads done, P staged
        // Load V tile over K tile
        for (int it = tid; it < KT*32; it += 256) {
            const int row = it >> 5;
            const int c4  = (it & 31) * 4;
            *(float4*)&KVs[row*LDQ + c4] = *(const float4*)&Vb[(size_t)(kt+row)*DD + c4];
        }
        __syncthreads();

        // PV: acc[i][0..7] += P[r0+i][k] * V[k][cg*8 .. cg*8+7]
#pragma unroll 4
        for (int k = 0; k < KT; k++) {
            const float4 v0 = *(float4*)&KVs[k*LDQ + cg*8];
            const float4 v1 = *(float4*)&KVs[k*LDQ + cg*8 + 4];
#pragma unroll
            for (int i = 0; i < 4; i++) {
                const float pk = Ps[(r0+i)*KT + k];
                acc[i][0] += pk*v0.x; acc[i][1] += pk*v0.y;
                acc[i][2] += pk*v0.z; acc[i][3] += pk*v0.w;
                acc[i][4] += pk*v1.x; acc[i][5] += pk*v1.y;
                acc[i][6] += pk*v1.z; acc[i][7] += pk*v1.w;
            }
        }
    }

    // Write out: [B, S, E] with e = h*128 + cg*8 + j
    const int bI = bh >> 4;
    const int h  = bh & 15;
#pragma unroll
    for (int i = 0; i < 4; i++) {
        const int srow = q0 + r0 + i;
        const float inv = 1.0f / l_i[i];
        float* dst = &Aout[((size_t)(bI*SS + srow))*EE + h*DD + cg*8];
#pragma unroll
        for (int j = 0; j < 8; j++) dst[j] = acc[i][j]*inv;
    }
}

// ---------------------------------------------------------------------------
extern "C" void kernel_launch(void* const* d_in, const int* in_sizes, int n_in,
                              void* d_out, int out_size)
{
    const float* query  = (const float*)d_in[0];
    const float* key_in = (const float*)d_in[1];
    const float* value  = (const float*)d_in[2];
    const float* Wq = (const float*)d_in[3];
    const float* bq = (const float*)d_in[4];
    const float* Wk = (const float*)d_in[5];
    const float* bk = (const float*)d_in[6];
    const float* Wv = (const float*)d_in[7];
    const float* bv = (const float*)d_in[8];
    const float* Wo = (const float*)d_in[9];
    const float* bo = (const float*)d_in[10];
    float* out = (float*)d_out;

    float *Qp, *Kp, *Vp, *Ap;
    cudaGetSymbolAddress((void**)&Qp, g_Q);
    cudaGetSymbolAddress((void**)&Kp, g_K);
    cudaGetSymbolAddress((void**)&Vp, g_V);
    cudaGetSymbolAddress((void**)&Ap, g_A);

    dim3 gg(EE/128, MROWS/128);   // (16, 32)
    dim3 bb(256);

    gemm_kernel<1><<<gg, bb>>>(query,  Wq, bq, Qp);
    gemm_kernel<1><<<gg, bb>>>(key_in, Wk, bk, Kp);
    gemm_kernel<1><<<gg, bb>>>(value,  Wv, bv, Vp);

    cudaFuncSetAttribute(attn_kernel, cudaFuncAttributeMaxDynamicSharedMemorySize,
                         ATTN_SMEM_BYTES);
    dim3 ga(SS/QT, BB*HH);        // (32, 32)
    attn_kernel<<<ga, bb, ATTN_SMEM_BYTES>>>(Qp, Kp, Vp, Ap);

    gemm_kernel<0><<<gg, bb>>>(Ap, Wo, bo, out);
}

// round 4
// speedup vs baseline: 1.5308x; 1.5308x over previous
#include <cuda_runtime.h>
#include <cuda_bf16.h>
#include <cstdint>
#include <math.h>

#define BB 2
#define SS 2048
#define EE 2048
#define HH 16
#define DD 128
#define MROWS (BB*SS)   // 4096

// ---------------- device scratch ----------------
__device__ float g_Q[MROWS*EE];   // [B*H, S, D]
__device__ float g_K[MROWS*EE];
__device__ float g_V[MROWS*EE];
__device__ float g_A[MROWS*EE];   // attention out [B, S, E]
__device__ __nv_bfloat16 g_Xh[MROWS*EE];
__device__ __nv_bfloat16 g_Xl[MROWS*EE];
__device__ __nv_bfloat16 g_Wth[EE*EE];    // W^T hi  [n][k]
__device__ __nv_bfloat16 g_Wtl[EE*EE];    // W^T lo  [n][k]

// ---------------- sm_80-level primitives (legal at compute_103) ----------------
__device__ __forceinline__ uint32_t smem_u32(const void* p) {
    uint32_t a;
    asm("{ .reg .u64 t; cvta.to.shared.u64 t, %1; cvt.u32.u64 %0, t; }" : "=r"(a) : "l"(p));
    return a;
}
#define CP_ASYNC_16(dst_u32, src_ptr) \
    asm volatile("cp.async.cg.shared.global [%0], [%1], 16;" :: "r"(dst_u32), "l"(src_ptr))
#define CP_COMMIT() asm volatile("cp.async.commit_group;" ::: "memory")
#define CP_WAIT(n)  asm volatile("cp.async.wait_group %0;" :: "n"(n) : "memory")

__device__ __forceinline__ void mma16816(float* c, const uint32_t* a, const uint32_t* b) {
    asm volatile(
        "mma.sync.aligned.m16n8k16.row.col.f32.bf16.bf16.f32 "
        "{%0,%1,%2,%3}, {%4,%5,%6,%7}, {%8,%9}, {%0,%1,%2,%3};"
        : "+f"(c[0]), "+f"(c[1]), "+f"(c[2]), "+f"(c[3])
        : "r"(a[0]), "r"(a[1]), "r"(a[2]), "r"(a[3]), "r"(b[0]), "r"(b[1]));
}

// ---------------------------------------------------------------------------
// Conversion kernels
// ---------------------------------------------------------------------------
__global__ __launch_bounds__(256)
void split_kernel(const float* __restrict__ X, __nv_bfloat16* __restrict__ H,
                  __nv_bfloat16* __restrict__ L, int n4)
{
    int i = blockIdx.x * blockDim.x + threadIdx.x;
    const int stride = gridDim.x * blockDim.x;
    for (; i < n4; i += stride) {
        float4 v = ((const float4*)X)[i];
        __nv_bfloat16 h0 = __float2bfloat16(v.x), h1 = __float2bfloat16(v.y);
        __nv_bfloat16 h2 = __float2bfloat16(v.z), h3 = __float2bfloat16(v.w);
        __nv_bfloat162 ph0; ph0.x = h0; ph0.y = h1;
        __nv_bfloat162 ph1; ph1.x = h2; ph1.y = h3;
        ((__nv_bfloat162*)H)[2*i]   = ph0;
        ((__nv_bfloat162*)H)[2*i+1] = ph1;
        __nv_bfloat162 pl0, pl1;
        pl0.x = __float2bfloat16(v.x - __bfloat162float(h0));
        pl0.y = __float2bfloat16(v.y - __bfloat162float(h1));
        pl1.x = __float2bfloat16(v.z - __bfloat162float(h2));
        pl1.y = __float2bfloat16(v.w - __bfloat162float(h3));
        ((__nv_bfloat162*)L)[2*i]   = pl0;
        ((__nv_bfloat162*)L)[2*i+1] = pl1;
    }
}

// W [k][n] fp32 -> Wt hi/lo [n][k] bf16
__global__ __launch_bounds__(1024)
void transpose_split_kernel(const float* __restrict__ W,
                            __nv_bfloat16* __restrict__ Th,
                            __nv_bfloat16* __restrict__ Tl)
{
    __shared__ float t[32][33];
    const int n0 = blockIdx.x * 32, k0 = blockIdx.y * 32;
    const int tx = threadIdx.x, ty = threadIdx.y;
    t[ty][tx] = W[(size_t)(k0 + ty) * EE + n0 + tx];
    __syncthreads();
    float v = t[tx][ty];              // = W[k0+tx][n0+ty]
    const int n = n0 + ty, k = k0 + tx;
    __nv_bfloat16 h = __float2bfloat16(v);
    Th[(size_t)n * EE + k] = h;
    Tl[(size_t)n * EE + k] = __float2bfloat16(v - __bfloat162float(h));
}

// ---------------------------------------------------------------------------
// Split-bf16 mma.sync GEMM:  Y[m][n] = sum_k X[m][k]*Wt[n][k] + bias[n]
// Block 128x256, BK=32, cp.async double-buffered, 8 warps (2m x 4n), warp 64x64.
// Smem tiles stored [row][k], row stride 112B (16B-aligned, conflict-free LDS).
// ---------------------------------------------------------------------------
#define BM 128
#define BN 256
#define BK 32
#define ROWB 112                       // bytes per smem row (32 bf16 data + pad)
#define A_BYTES (BM*ROWB)              // 14336
#define B_BYTES (BN*ROWB)              // 28672
#define STAGE_BYTES (2*A_BYTES + 2*B_BYTES)   // Ah, Al, Bh, Bl = 86016
#define GEMM_SMEM (2*STAGE_BYTES)             // 172032

template<int OUT_HEADMAJOR>
__global__ __launch_bounds__(256)
void gemm_mma_kernel(const __nv_bfloat16* __restrict__ Xh, const __nv_bfloat16* __restrict__ Xl,
                     const __nv_bfloat16* __restrict__ Wh, const __nv_bfloat16* __restrict__ Wl,
                     const float* __restrict__ bias, float* __restrict__ Y)
{
    extern __shared__ char sm[];
    const int tid  = threadIdx.x;
    const int lane = tid & 31;
    const int wid  = tid >> 5;
    const int g    = lane >> 2;       // group row 0..7
    const int tig  = lane & 3;        // thread-in-group

    const int m0 = blockIdx.y * BM;
    const int n0 = blockIdx.x * BN;

    const int wm = (wid & 1) * 64;    // warp m offset
    const int wn = (wid >> 1) * 64;   // warp n offset

    const uint32_t smb = smem_u32(sm);

    float c[4][8][4];
#pragma unroll
    for (int i = 0; i < 4; i++)
#pragma unroll
        for (int j = 0; j < 8; j++)
#pragma unroll
            for (int q = 0; q < 4; q++) c[i][j][q] = 0.f;

    const __nv_bfloat16* srcA[2] = { Xh + (size_t)m0*EE, Xl + (size_t)m0*EE };
    const __nv_bfloat16* srcB[2] = { Wh + (size_t)n0*EE, Wl + (size_t)n0*EE };

    // ---- async stage loader: stage s covers k = s*BK ----
    auto load_stage = [&](int s) {
        const int buf = s & 1;
        const uint32_t base = smb + buf * STAGE_BYTES;
        const int k0 = s * BK;
        // A hi/lo: 128 rows x 4 chunks of 16B, 512 chunks each -> 2/thread
#pragma unroll
        for (int v = 0; v < 2; v++) {
            const __nv_bfloat16* src = srcA[v] + k0;
            const uint32_t dst0 = base + v * A_BYTES;
#pragma unroll
            for (int i = 0; i < 2; i++) {
                int idx = tid + i * 256;          // 0..511
                int r = idx >> 2, ch = idx & 3;
                CP_ASYNC_16(dst0 + r * ROWB + ch * 16, src + (size_t)r * EE + ch * 8);
            }
        }
        // B hi/lo: 256 rows x 4 chunks, 1024 chunks each -> 4/thread
#pragma unroll
        for (int v = 0; v < 2; v++) {
            const __nv_bfloat16* src = srcB[v] + k0;
            const uint32_t dst0 = base + 2 * A_BYTES + v * B_BYTES;
#pragma unroll
            for (int i = 0; i < 4; i++) {
                int idx = tid + i * 256;          // 0..1023
                int r = idx >> 2, ch = idx & 3;
                CP_ASYNC_16(dst0 + r * ROWB + ch * 16, src + (size_t)r * EE + ch * 8);
            }
        }
        CP_COMMIT();
    };

    const int NS = EE / BK;   // 64
    load_stage(0);

    for (int s = 0; s < NS; s++) {
        const int buf = s & 1;
        if (s + 1 < NS) { load_stage(s + 1); CP_WAIT(1); }
        else            { CP_WAIT(0); }
        __syncthreads();

        const char* Ah = sm + buf * STAGE_BYTES;
        const char* Al = Ah + A_BYTES;
        const char* Bh = Ah + 2 * A_BYTES;
        const char* Bl = Bh + B_BYTES;

#pragma unroll
        for (int kb = 0; kb < BK; kb += 16) {
            uint32_t ah[4][4], al[4][4], bh[8][2], bl[8][2];
#pragma unroll
            for (int mt = 0; mt < 4; mt++) {
                const int r = wm + mt * 16 + g;
                const char* p = Ah + r * ROWB + kb * 2 + tig * 4;
                ah[mt][0] = *(const uint32_t*)p;
                ah[mt][1] = *(const uint32_t*)(p + 8 * ROWB);
                ah[mt][2] = *(const uint32_t*)(p + 16);
                ah[mt][3] = *(const uint32_t*)(p + 8 * ROWB + 16);
                const char* q = Al + r * ROWB + kb * 2 + tig * 4;
                al[mt][0] = *(const uint32_t*)q;
                al[mt][1] = *(const uint32_t*)(q + 8 * ROWB);
                al[mt][2] = *(const uint32_t*)(q + 16);
                al[mt][3] = *(const uint32_t*)(q + 8 * ROWB + 16);
            }
#pragma unroll
            for (int nt = 0; nt < 8; nt++) {
                const int r = wn + nt * 8 + g;
                const char* p = Bh + r * ROWB + kb * 2 + tig * 4;
                bh[nt][0] = *(const uint32_t*)p;
                bh[nt][1] = *(const uint32_t*)(p + 16);
                const char* q = Bl + r * ROWB + kb * 2 + tig * 4;
                bl[nt][0] = *(const uint32_t*)q;
                bl[nt][1] = *(const uint32_t*)(q + 16);
            }
#pragma unroll
            for (int mt = 0; mt < 4; mt++)
#pragma unroll
                for (int nt = 0; nt < 8; nt++) {
                    mma16816(c[mt][nt], ah[mt], bh[nt]);
                    mma16816(c[mt][nt], ah[mt], bl[nt]);
                    mma16816(c[mt][nt], al[mt], bh[nt]);
                }
        }
        __syncthreads();
    }

    // ---- epilogue: bias + store ----
#pragma unroll
    for (int mt = 0; mt < 4; mt++) {
        const int m = m0 + wm + mt * 16 + g;
        const int bI = m >> 11;
        const int sI = m & (SS - 1);
#pragma unroll
        for (int nt = 0; nt < 8; nt++) {
            const int n = n0 + wn + nt * 8 + 2 * tig;
            const float b0 = bias[n], b1 = bias[n + 1];
            size_t o0, o1;
            if (OUT_HEADMAJOR) {
                const int h = n >> 7, d = n & 127;
                o0 = (((size_t)(bI * HH + h) * SS + sI) * DD) + d;
                o1 = o0 + 8 * DD;
            } else {
                o0 = (size_t)m * EE + n;
                o1 = o0 + 8 * EE;
            }
            float2 v0; v0.x = c[mt][nt][0] + b0; v0.y = c[mt][nt][1] + b1;
            float2 v1; v1.x = c[mt][nt][2] + b0; v1.y = c[mt][nt][3] + b1;
            *(float2*)&Y[o0] = v0;     // rows m
            *(float2*)&Y[o1] = v1;     // rows m+8
        }
    }
}

// ---------------------------------------------------------------------------
// Flash attention (fp32, online softmax) — unchanged
// ---------------------------------------------------------------------------
#define QT 64
#define KT 64
#define LDQ 132
#define ATTN_SMEM_FLOATS (QT*LDQ + KT*LDQ + QT*KT)
#define ATTN_SMEM_BYTES  (ATTN_SMEM_FLOATS * 4)

__global__ __launch_bounds__(256)
void attn_kernel(const float* __restrict__ Q, const float* __restrict__ K,
                 const float* __restrict__ V, float* __restrict__ Aout)
{
    extern __shared__ float smf[];
    float* Qs  = smf;
    float* KVs = smf + QT*LDQ;
    float* Ps  = smf + QT*LDQ + KT*LDQ;

    const int tid = threadIdx.x;
    const int bh  = blockIdx.y;
    const int q0  = blockIdx.x * QT;

    const float* Qb = Q + (size_t)bh*SS*DD;
    const float* Kb = K + (size_t)bh*SS*DD;
    const float* Vb = V + (size_t)bh*SS*DD;

    for (int it = tid; it < QT*32; it += 256) {
        const int row = it >> 5;
        const int c4  = (it & 31) * 4;
        *(float4*)&Qs[row*LDQ + c4] = *(const float4*)&Qb[(size_t)(q0+row)*DD + c4];
    }

    const int rg = tid >> 4, cg = tid & 15;
    const int r0 = rg * 4, c0 = cg * 4;
    const float scale = 0.08838834764831845f;

    float m_i[4], l_i[4], acc[4][8];
#pragma unroll
    for (int i = 0; i < 4; i++) {
        m_i[i] = -INFINITY; l_i[i] = 0.f;
#pragma unroll
        for (int j = 0; j < 8; j++) acc[i][j] = 0.f;
    }

    for (int kt = 0; kt < SS; kt += KT) {
        __syncthreads();
        for (int it = tid; it < KT*32; it += 256) {
            const int row = it >> 5;
            const int c4  = (it & 31) * 4;
            *(float4*)&KVs[row*LDQ + c4] = *(const float4*)&Kb[(size_t)(kt+row)*DD + c4];
        }
        __syncthreads();

        float s[4][4];
#pragma unroll
        for (int i = 0; i < 4; i++)
#pragma unroll
            for (int j = 0; j < 4; j++) s[i][j] = 0.f;

#pragma unroll 8
        for (int d = 0; d < DD; d += 4) {
            float4 qv[4], kv[4];
#pragma unroll
            for (int i = 0; i < 4; i++) qv[i] = *(float4*)&Qs[(r0+i)*LDQ + d];
#pragma unroll
            for (int j = 0; j < 4; j++) kv[j] = *(float4*)&KVs[(c0+j)*LDQ + d];
#pragma unroll
            for (int i = 0; i < 4; i++)
#pragma unroll
                for (int j = 0; j < 4; j++) {
                    s[i][j] += qv[i].x*kv[j].x;
                    s[i][j] += qv[i].y*kv[j].y;
                    s[i][j] += qv[i].z*kv[j].z;
                    s[i][j] += qv[i].w*kv[j].w;
                }
        }
#pragma unroll
        for (int i = 0; i < 4; i++)
#pragma unroll
            for (int j = 0; j < 4; j++) s[i][j] *= scale;

        float mnew[4];
#pragma unroll
        for (int i = 0; i < 4; i++) {
            float mx = fmaxf(fmaxf(s[i][0], s[i][1]), fmaxf(s[i][2], s[i][3]));
            mx = fmaxf(mx, __shfl_xor_sync(0xffffffffu, mx, 8));
            mx = fmaxf(mx, __shfl_xor_sync(0xffffffffu, mx, 4));
            mx = fmaxf(mx, __shfl_xor_sync(0xffffffffu, mx, 2));
            mx = fmaxf(mx, __shfl_xor_sync(0xffffffffu, mx, 1));
            mnew[i] = fmaxf(m_i[i], mx);
        }

        float p[4][4], rs[4];
#pragma unroll
        for (int i = 0; i < 4; i++) {
            const float alpha = __expf(m_i[i] - mnew[i]);
            m_i[i] = mnew[i];
            rs[i] = 0.f;
#pragma unroll
            for (int j = 0; j < 4; j++) {
                p[i][j] = __expf(s[i][j] - mnew[i]);
                rs[i] += p[i][j];
            }
            rs[i] += __shfl_xor_sync(0xffffffffu, rs[i], 8);
            rs[i] += __shfl_xor_sync(0xffffffffu, rs[i], 4);
            rs[i] += __shfl_xor_sync(0xffffffffu, rs[i], 2);
            rs[i] += __shfl_xor_sync(0xffffffffu, rs[i], 1);
            l_i[i] = l_i[i]*alpha + rs[i];
#pragma unroll
            for (int j = 0; j < 8; j++) acc[i][j] *= alpha;
        }

#pragma unroll
        for (int i = 0; i < 4; i++)
#pragma unroll
            for (int j = 0; j < 4; j++)
                Ps[(r0+i)*KT + (c0+j)] = p[i][j];

        __syncthreads();
        for (int it = tid; it < KT*32; it += 256) {
            const int row = it >> 5;
            const int c4  = (it & 31) * 4;
            *(float4*)&KVs[row*LDQ + c4] = *(const float4*)&Vb[(size_t)(kt+row)*DD + c4];
        }
        __syncthreads();

#pragma unroll 4
        for (int k = 0; k < KT; k++) {
            const float4 v0 = *(float4*)&KVs[k*LDQ + cg*8];
            const float4 v1 = *(float4*)&KVs[k*LDQ + cg*8 + 4];
#pragma unroll
            for (int i = 0; i < 4; i++) {
                const float pk = Ps[(r0+i)*KT + k];
                acc[i][0] += pk*v0.x; acc[i][1] += pk*v0.y;
                acc[i][2] += pk*v0.z; acc[i][3] += pk*v0.w;
                acc[i][4] += pk*v1.x; acc[i][5] += pk*v1.y;
                acc[i][6] += pk*v1.z; acc[i][7] += pk*v1.w;
            }
        }
    }

    const int bI = bh >> 4;
    const int h  = bh & 15;
#pragma unroll
    for (int i = 0; i < 4; i++) {
        const int srow = q0 + r0 + i;
        const float inv = 1.0f / l_i[i];
        float* dst = &Aout[((size_t)(bI*SS + srow))*EE + h*DD + cg*8];
#pragma unroll
        for (int j = 0; j < 8; j++) dst[j] = acc[i][j]*inv;
    }
}

// ---------------------------------------------------------------------------
extern "C" void kernel_launch(void* const* d_in, const int* in_sizes, int n_in,
                              void* d_out, int out_size)
{
    const float* query  = (const float*)d_in[0];
    const float* key_in = (const float*)d_in[1];
    const float* value  = (const float*)d_in[2];
    const float* Wq = (const float*)d_in[3];
    const float* bq = (const float*)d_in[4];
    const float* Wk = (const float*)d_in[5];
    const float* bk = (const float*)d_in[6];
    const float* Wv = (const float*)d_in[7];
    const float* bv = (const float*)d_in[8];
    const float* Wo = (const float*)d_in[9];
    const float* bo = (const float*)d_in[10];
    float* out = (float*)d_out;

    float *Qp, *Kp, *Vp, *Ap;
    __nv_bfloat16 *Xh, *Xl, *Wth, *Wtl;
    cudaGetSymbolAddress((void**)&Qp, g_Q);
    cudaGetSymbolAddress((void**)&Kp, g_K);
    cudaGetSymbolAddress((void**)&Vp, g_V);
    cudaGetSymbolAddress((void**)&Ap, g_A);
    cudaGetSymbolAddress((void**)&Xh, g_Xh);
    cudaGetSymbolAddress((void**)&Xl, g_Xl);
    cudaGetSymbolAddress((void**)&Wth, g_Wth);
    cudaGetSymbolAddress((void**)&Wtl, g_Wtl);

    cudaFuncSetAttribute(gemm_mma_kernel<1>, cudaFuncAttributeMaxDynamicSharedMemorySize, GEMM_SMEM);
    cudaFuncSetAttribute(gemm_mma_kernel<0>, cudaFuncAttributeMaxDynamicSharedMemorySize, GEMM_SMEM);
    cudaFuncSetAttribute(attn_kernel, cudaFuncAttributeMaxDynamicSharedMemorySize, ATTN_SMEM_BYTES);

    const int n4 = MROWS * EE / 4;
    dim3 gt(EE/32, EE/32), bt(32, 32);
    dim3 gg(EE/BN, MROWS/BM);         // (8, 32) = 256 blocks

    // Q projection
    split_kernel<<<2048, 256>>>(query, Xh, Xl, n4);
    transpose_split_kernel<<<gt, bt>>>(Wq, Wth, Wtl);
    gemm_mma_kernel<1><<<gg, 256, GEMM_SMEM>>>(Xh, Xl, Wth, Wtl, bq, Qp);
    // K projection
    split_kernel<<<2048, 256>>>(key_in, Xh, Xl, n4);
    transpose_split_kernel<<<gt, bt>>>(Wk, Wth, Wtl);
    gemm_mma_kernel<1><<<gg, 256, GEMM_SMEM>>>(Xh, Xl, Wth, Wtl, bk, Kp);
    // V projection
    split_kernel<<<2048, 256>>>(value, Xh, Xl, n4);
    transpose_split_kernel<<<gt, bt>>>(Wv, Wth, Wtl);
    gemm_mma_kernel<1><<<gg, 256, GEMM_SMEM>>>(Xh, Xl, Wth, Wtl, bv, Vp);

    // attention
    dim3 ga(SS/QT, BB*HH);
    attn_kernel<<<ga, 256, ATTN_SMEM_BYTES>>>(Qp, Kp, Vp, Ap);

    // output projection
    split_kernel<<<2048, 256>>>(Ap, Xh, Xl, n4);
    transpose_split_kernel<<<gt, bt>>>(Wo, Wth, Wtl);
    gemm_mma_kernel<0><<<gg, 256, GEMM_SMEM>>>(Xh, Xl, Wth, Wtl, bo, out);
}

// round 5
// speedup vs baseline: 3.4424x; 2.2488x over previous
#include <cuda_runtime.h>
#include <cuda_bf16.h>
#include <cstdint>
#include <math.h>

#define BB 2
#define SS 2048
#define EE 2048
#define HH 16
#define DD 128
#define MROWS (BB*SS)   // 4096

// ---------------- device scratch ----------------
__device__ __nv_bfloat16 g_Qh[MROWS*EE];  // [B*H, S, D]
__device__ __nv_bfloat16 g_Ql[MROWS*EE];
__device__ __nv_bfloat16 g_Kh[MROWS*EE];  // [B*H, S, D]
__device__ __nv_bfloat16 g_Kl[MROWS*EE];
__device__ __nv_bfloat16 g_Vh[MROWS*EE];  // [B*H, D, S] (transposed)
__device__ __nv_bfloat16 g_Vl[MROWS*EE];
__device__ __nv_bfloat16 g_Xh[MROWS*EE];  // activation split hi [m][k]
__device__ __nv_bfloat16 g_Xl[MROWS*EE];
__device__ __nv_bfloat16 g_Wth[EE*EE];    // W^T hi [n][k]
__device__ __nv_bfloat16 g_Wtl[EE*EE];

// ---------------- primitives ----------------
__device__ __forceinline__ uint32_t smem_u32(const void* p) {
    uint32_t a;
    asm("{ .reg .u64 t; cvta.to.shared.u64 t, %1; cvt.u32.u64 %0, t; }" : "=r"(a) : "l"(p));
    return a;
}
#define CP_ASYNC_16(dst_u32, src_ptr) \
    asm volatile("cp.async.cg.shared.global [%0], [%1], 16;" :: "r"(dst_u32), "l"(src_ptr))
#define CP_COMMIT() asm volatile("cp.async.commit_group;" ::: "memory")
#define CP_WAIT(n)  asm volatile("cp.async.wait_group %0;" :: "n"(n) : "memory")

__device__ __forceinline__ void mma16816(float* c, const uint32_t* a, const uint32_t* b) {
    asm volatile(
        "mma.sync.aligned.m16n8k16.row.col.f32.bf16.bf16.f32 "
        "{%0,%1,%2,%3}, {%4,%5,%6,%7}, {%8,%9}, {%0,%1,%2,%3};"
        : "+f"(c[0]), "+f"(c[1]), "+f"(c[2]), "+f"(c[3])
        : "r"(a[0]), "r"(a[1]), "r"(a[2]), "r"(a[3]), "r"(b[0]), "r"(b[1]));
}

// pack two floats into bf16x2 hi, and their residuals into bf16x2 lo
__device__ __forceinline__ uint32_t pack_split(float x, float y, uint32_t& lo) {
    __nv_bfloat162 hp, lp;
    hp.x = __float2bfloat16(x);
    hp.y = __float2bfloat16(y);
    lp.x = __float2bfloat16(x - __bfloat162float(hp.x));
    lp.y = __float2bfloat16(y - __bfloat162float(hp.y));
    lo = *(uint32_t*)&lp;
    return *(uint32_t*)&hp;
}

// ---------------------------------------------------------------------------
// Conversion kernels
// ---------------------------------------------------------------------------
__global__ __launch_bounds__(256)
void split_kernel(const float* __restrict__ X, __nv_bfloat16* __restrict__ H,
                  __nv_bfloat16* __restrict__ L, int n4)
{
    int i = blockIdx.x * blockDim.x + threadIdx.x;
    const int stride = gridDim.x * blockDim.x;
    for (; i < n4; i += stride) {
        float4 v = ((const float4*)X)[i];
        uint32_t l0, l1;
        uint32_t h0 = pack_split(v.x, v.y, l0);
        uint32_t h1 = pack_split(v.z, v.w, l1);
        ((uint32_t*)H)[2*i]   = h0;
        ((uint32_t*)H)[2*i+1] = h1;
        ((uint32_t*)L)[2*i]   = l0;
        ((uint32_t*)L)[2*i+1] = l1;
    }
}

// W [k][n] fp32 -> Wt hi/lo [n][k] bf16
__global__ __launch_bounds__(1024)
void transpose_split_kernel(const float* __restrict__ W,
                            __nv_bfloat16* __restrict__ Th,
                            __nv_bfloat16* __restrict__ Tl)
{
    __shared__ float t[32][33];
    const int n0 = blockIdx.x * 32, k0 = blockIdx.y * 32;
    const int tx = threadIdx.x, ty = threadIdx.y;
    t[ty][tx] = W[(size_t)(k0 + ty) * EE + n0 + tx];
    __syncthreads();
    float v = t[tx][ty];
    const int n = n0 + ty, k = k0 + tx;
    __nv_bfloat16 h = __float2bfloat16(v);
    Th[(size_t)n * EE + k] = h;
    Tl[(size_t)n * EE + k] = __float2bfloat16(v - __bfloat162float(h));
}

// ---------------------------------------------------------------------------
// Split-bf16 mma.sync GEMM. MODE 0: fp32 [m][n] out. MODE 1: bf16 split
// head-major [B*H,S,D]. MODE 2: bf16 split head-major TRANSPOSED [B*H,D,S].
// ---------------------------------------------------------------------------
#define BM 128
#define BN 256
#define BK 32
#define ROWB 112
#define A_BYTES (BM*ROWB)
#define B_BYTES (BN*ROWB)
#define STAGE_BYTES (2*A_BYTES + 2*B_BYTES)
#define GEMM_SMEM (2*STAGE_BYTES)

template<int MODE>
__global__ __launch_bounds__(256)
void gemm_mma_kernel(const __nv_bfloat16* __restrict__ Xh, const __nv_bfloat16* __restrict__ Xl,
                     const __nv_bfloat16* __restrict__ Wh, const __nv_bfloat16* __restrict__ Wl,
                     const float* __restrict__ bias, float* __restrict__ Yf,
                     __nv_bfloat16* __restrict__ Yh, __nv_bfloat16* __restrict__ Yl)
{
    extern __shared__ char sm[];
    const int tid  = threadIdx.x;
    const int lane = tid & 31;
    const int wid  = tid >> 5;
    const int g    = lane >> 2;
    const int tig  = lane & 3;

    const int m0 = blockIdx.y * BM;
    const int n0 = blockIdx.x * BN;
    const int wm = (wid & 1) * 64;
    const int wn = (wid >> 1) * 64;

    const uint32_t smb = smem_u32(sm);

    float c[4][8][4];
#pragma unroll
    for (int i = 0; i < 4; i++)
#pragma unroll
        for (int j = 0; j < 8; j++)
#pragma unroll
            for (int q = 0; q < 4; q++) c[i][j][q] = 0.f;

    const __nv_bfloat16* srcA[2] = { Xh + (size_t)m0*EE, Xl + (size_t)m0*EE };
    const __nv_bfloat16* srcB[2] = { Wh + (size_t)n0*EE, Wl + (size_t)n0*EE };

    auto load_stage = [&](int s) {
        const int buf = s & 1;
        const uint32_t base = smb + buf * STAGE_BYTES;
        const int k0 = s * BK;
#pragma unroll
        for (int v = 0; v < 2; v++) {
            const __nv_bfloat16* src = srcA[v] + k0;
            const uint32_t dst0 = base + v * A_BYTES;
#pragma unroll
            for (int i = 0; i < 2; i++) {
                int idx = tid + i * 256;
                int r = idx >> 2, ch = idx & 3;
                CP_ASYNC_16(dst0 + r * ROWB + ch * 16, src + (size_t)r * EE + ch * 8);
            }
        }
#pragma unroll
        for (int v = 0; v < 2; v++) {
            const __nv_bfloat16* src = srcB[v] + k0;
            const uint32_t dst0 = base + 2 * A_BYTES + v * B_BYTES;
#pragma unroll
            for (int i = 0; i < 4; i++) {
                int idx = tid + i * 256;
                int r = idx >> 2, ch = idx & 3;
                CP_ASYNC_16(dst0 + r * ROWB + ch * 16, src + (size_t)r * EE + ch * 8);
            }
        }
        CP_COMMIT();
    };

    const int NS = EE / BK;
    load_stage(0);

    for (int s = 0; s < NS; s++) {
        const int buf = s & 1;
        if (s + 1 < NS) { load_stage(s + 1); CP_WAIT(1); }
        else            { CP_WAIT(0); }
        __syncthreads();

        const char* Ah = sm + buf * STAGE_BYTES;
        const char* Al = Ah + A_BYTES;
        const char* Bh = Ah + 2 * A_BYTES;
        const char* Bl = Bh + B_BYTES;

#pragma unroll
        for (int kb = 0; kb < BK; kb += 16) {
            uint32_t ah[4][4], al[4][4], bh[8][2], bl[8][2];
#pragma unroll
            for (int mt = 0; mt < 4; mt++) {
                const int r = wm + mt * 16 + g;
                const char* p = Ah + r * ROWB + kb * 2 + tig * 4;
                ah[mt][0] = *(const uint32_t*)p;
                ah[mt][1] = *(const uint32_t*)(p + 8 * ROWB);
                ah[mt][2] = *(const uint32_t*)(p + 16);
                ah[mt][3] = *(const uint32_t*)(p + 8 * ROWB + 16);
                const char* q = Al + r * ROWB + kb * 2 + tig * 4;
                al[mt][0] = *(const uint32_t*)q;
                al[mt][1] = *(const uint32_t*)(q + 8 * ROWB);
                al[mt][2] = *(const uint32_t*)(q + 16);
                al[mt][3] = *(const uint32_t*)(q + 8 * ROWB + 16);
            }
#pragma unroll
            for (int nt = 0; nt < 8; nt++) {
                const int r = wn + nt * 8 + g;
                const char* p = Bh + r * ROWB + kb * 2 + tig * 4;
                bh[nt][0] = *(const uint32_t*)p;
                bh[nt][1] = *(const uint32_t*)(p + 16);
                const char* q = Bl + r * ROWB + kb * 2 + tig * 4;
                bl[nt][0] = *(const uint32_t*)q;
                bl[nt][1] = *(const uint32_t*)(q + 16);
            }
#pragma unroll
            for (int mt = 0; mt < 4; mt++)
#pragma unroll
                for (int nt = 0; nt < 8; nt++) {
                    mma16816(c[mt][nt], ah[mt], bh[nt]);
                    mma16816(c[mt][nt], ah[mt], bl[nt]);
                    mma16816(c[mt][nt], al[mt], bh[nt]);
                }
        }
        __syncthreads();
    }

    // ---- epilogue ----
#pragma unroll
    for (int mt = 0; mt < 4; mt++) {
        const int m = m0 + wm + mt * 16 + g;
        const int bI = m >> 11;
        const int sI = m & (SS - 1);
#pragma unroll
        for (int nt = 0; nt < 8; nt++) {
            const int n = n0 + wn + nt * 8 + 2 * tig;
            const float b0 = bias[n], b1 = bias[n + 1];
            const float y0 = c[mt][nt][0] + b0, y1 = c[mt][nt][1] + b1;
            const float y2 = c[mt][nt][2] + b0, y3 = c[mt][nt][3] + b1;
            if (MODE == 0) {
                size_t o0 = (size_t)m * EE + n;
                float2 v0; v0.x = y0; v0.y = y1;
                float2 v1; v1.x = y2; v1.y = y3;
                *(float2*)&Yf[o0] = v0;
                *(float2*)&Yf[o0 + 8 * EE] = v1;
            } else if (MODE == 1) {
                const int h = n >> 7, d = n & 127;
                size_t o0 = (((size_t)(bI * HH + h) * SS + sI) * DD) + d;
                uint32_t lo, hi;
                hi = pack_split(y0, y1, lo);
                *(uint32_t*)&Yh[o0] = hi; *(uint32_t*)&Yl[o0] = lo;
                hi = pack_split(y2, y3, lo);
                *(uint32_t*)&Yh[o0 + 8 * DD] = hi; *(uint32_t*)&Yl[o0 + 8 * DD] = lo;
            } else {
                const int h = n >> 7, d = n & 127;
                const size_t base = (size_t)(bI * HH + h) * DD;
                size_t o00 = (base + d) * SS + sI;
                size_t o01 = (base + d + 1) * SS + sI;
                __nv_bfloat16 t;
                t = __float2bfloat16(y0); Yh[o00] = t;
                Yl[o00] = __float2bfloat16(y0 - __bfloat162float(t));
                t = __float2bfloat16(y1); Yh[o01] = t;
                Yl[o01] = __float2bfloat16(y1 - __bfloat162float(t));
                t = __float2bfloat16(y2); Yh[o00 + 8] = t;
                Yl[o00 + 8] = __float2bfloat16(y2 - __bfloat162float(t));
                t = __float2bfloat16(y3); Yh[o01 + 8] = t;
                Yl[o01 + 8] = __float2bfloat16(y3 - __bfloat162float(t));
            }
        }
    }
}

// ---------------------------------------------------------------------------
// Flash attention with split-bf16 mma.sync.
// Q,K: [B*H,S,D] hi/lo. V: [B*H,D,S] hi/lo (transposed). Out -> Xh/Xl [B,S,E].
// Block: 256 thr (8 warps), 128 q-rows; iterate 64-key tiles.
// ---------------------------------------------------------------------------
#define AQT 128
#define AKT 64
#define ROWK 272   // 128 bf16 + 16B pad
#define ROWV 144   // 64 bf16 + 16B pad
#define SM_KL (64*ROWK)
#define SM_VH (2*64*ROWK)
#define SM_VL (SM_VH + 128*ROWV)
#define ATTN_SMEM (SM_VL + 128*ROWV)   // 71680

__global__ __launch_bounds__(256)
void attn_mma_kernel(const __nv_bfloat16* __restrict__ Qh_, const __nv_bfloat16* __restrict__ Ql_,
                     const __nv_bfloat16* __restrict__ Kh_, const __nv_bfloat16* __restrict__ Kl_,
                     const __nv_bfloat16* __restrict__ Vh_, const __nv_bfloat16* __restrict__ Vl_,
                     __nv_bfloat16* __restrict__ Xh, __nv_bfloat16* __restrict__ Xl)
{
    extern __shared__ char sm[];
    const uint32_t smb = smem_u32(sm);
    const int tid  = threadIdx.x;
    const int lane = tid & 31;
    const int wid  = tid >> 5;
    const int g    = lane >> 2;
    const int tig  = lane & 3;

    const int bh = blockIdx.y;
    const int q0 = blockIdx.x * AQT;
    const size_t hoff = (size_t)bh * SS * DD;

    // ---- Phase 1: Q tile (128x128 hi/lo) to smem, then to fragments ----
    {
        const __nv_bfloat16* qsrc[2] = { Qh_ + hoff + (size_t)q0 * DD,
                                         Ql_ + hoff + (size_t)q0 * DD };
#pragma unroll
        for (int v = 0; v < 2; v++) {
            const uint32_t dst0 = smb + v * (128 * ROWK);
#pragma unroll
            for (int i = 0; i < 8; i++) {
                int idx = tid + i * 256;          // 0..2047
                int row = idx >> 4, ch = idx & 15;
                CP_ASYNC_16(dst0 + row * ROWK + ch * 16, qsrc[v] + (size_t)row * DD + ch * 8);
            }
        }
        CP_COMMIT(); CP_WAIT(0);
        __syncthreads();
    }

    uint32_t qh[8][4], ql[8][4];
    {
        const int wrow = wid * 16 + g;
#pragma unroll
        for (int ks = 0; ks < 8; ks++) {
            const char* p = sm + wrow * ROWK + ks * 32 + tig * 4;
            qh[ks][0] = *(const uint32_t*)p;
            qh[ks][1] = *(const uint32_t*)(p + 8 * ROWK);
            qh[ks][2] = *(const uint32_t*)(p + 16);
            qh[ks][3] = *(const uint32_t*)(p + 8 * ROWK + 16);
            const char* q = p + 128 * ROWK;
            ql[ks][0] = *(const uint32_t*)q;
            ql[ks][1] = *(const uint32_t*)(q + 8 * ROWK);
            ql[ks][2] = *(const uint32_t*)(q + 16);
            ql[ks][3] = *(const uint32_t*)(q + 8 * ROWK + 16);
        }
    }
    __syncthreads();

    const __nv_bfloat16* ksrc[2] = { Kh_ + hoff, Kl_ + hoff };
    const __nv_bfloat16* vsrc[2] = { Vh_ + (size_t)bh * DD * SS, Vl_ + (size_t)bh * DD * SS };
    const float scale = 0.08838834764831845f;   // 1/sqrt(128)

    float m0 = -INFINITY, m1 = -INFINITY, l0 = 0.f, l1 = 0.f;
    float o[16][4];
#pragma unroll
    for (int dt = 0; dt < 16; dt++)
#pragma unroll
        for (int q = 0; q < 4; q++) o[dt][q] = 0.f;

    for (int kt = 0; kt < SS; kt += AKT) {
        // ---- load K (64x128) hi/lo and Vt (128x64) hi/lo ----
#pragma unroll
        for (int v = 0; v < 2; v++) {
            const uint32_t dst0 = smb + v * SM_KL;
#pragma unroll
            for (int i = 0; i < 4; i++) {
                int idx = tid + i * 256;          // 0..1023
                int row = idx >> 4, ch = idx & 15;
                CP_ASYNC_16(dst0 + row * ROWK + ch * 16,
                            ksrc[v] + (size_t)(kt + row) * DD + ch * 8);
            }
        }
#pragma unroll
        for (int v = 0; v < 2; v++) {
            const uint32_t dst0 = smb + SM_VH + v * (128 * ROWV);
#pragma unroll
            for (int i = 0; i < 4; i++) {
                int idx = tid + i * 256;          // 0..1023
                int row = idx >> 3, ch = idx & 7;
                CP_ASYNC_16(dst0 + row * ROWV + ch * 16,
                            vsrc[v] + (size_t)row * SS + kt + ch * 8);
            }
        }
        CP_COMMIT(); CP_WAIT(0);
        __syncthreads();

        // ---- scores: S = Q K^T (3-term split) ----
        float sc[8][4];
#pragma unroll
        for (int nt = 0; nt < 8; nt++)
#pragma unroll
            for (int q = 0; q < 4; q++) sc[nt][q] = 0.f;

#pragma unroll
        for (int nt = 0; nt < 8; nt++) {
            const char* kb = sm + (nt * 8 + g) * ROWK + tig * 4;
#pragma unroll
            for (int ks = 0; ks < 8; ks++) {
                uint32_t bhf[2], blf[2];
                bhf[0] = *(const uint32_t*)(kb + ks * 32);
                bhf[1] = *(const uint32_t*)(kb + ks * 32 + 16);
                blf[0] = *(const uint32_t*)(kb + SM_KL + ks * 32);
                blf[1] = *(const uint32_t*)(kb + SM_KL + ks * 32 + 16);
                mma16816(sc[nt], qh[ks], bhf);
                mma16816(sc[nt], qh[ks], blf);
                mma16816(sc[nt], ql[ks], bhf);
            }
        }

        // ---- online softmax ----
        float mx0 = -INFINITY, mx1 = -INFINITY;
#pragma unroll
        for (int nt = 0; nt < 8; nt++) {
            mx0 = fmaxf(mx0, fmaxf(sc[nt][0], sc[nt][1]));
            mx1 = fmaxf(mx1, fmaxf(sc[nt][2], sc[nt][3]));
        }
        mx0 = fmaxf(mx0, __shfl_xor_sync(0xffffffffu, mx0, 1));
        mx0 = fmaxf(mx0, __shfl_xor_sync(0xffffffffu, mx0, 2));
        mx1 = fmaxf(mx1, __shfl_xor_sync(0xffffffffu, mx1, 1));
        mx1 = fmaxf(mx1, __shfl_xor_sync(0xffffffffu, mx1, 2));

        const float mn0 = fmaxf(m0, mx0 * scale);
        const float mn1 = fmaxf(m1, mx1 * scale);
        const float a0 = __expf(m0 - mn0);
        const float a1 = __expf(m1 - mn1);
        m0 = mn0; m1 = mn1;

        float rs0 = 0.f, rs1 = 0.f;
        uint32_t ph[8][2], pl[8][2];
#pragma unroll
        for (int nt = 0; nt < 8; nt++) {
            float p0 = __expf(sc[nt][0] * scale - mn0);
            float p1 = __expf(sc[nt][1] * scale - mn0);
            float p2 = __expf(sc[nt][2] * scale - mn1);
            float p3 = __expf(sc[nt][3] * scale - mn1);
            rs0 += p0 + p1; rs1 += p2 + p3;
            ph[nt][0] = pack_split(p0, p1, pl[nt][0]);
            ph[nt][1] = pack_split(p2, p3, pl[nt][1]);
        }
        rs0 += __shfl_xor_sync(0xffffffffu, rs0, 1);
        rs0 += __shfl_xor_sync(0xffffffffu, rs0, 2);
        rs1 += __shfl_xor_sync(0xffffffffu, rs1, 1);
        rs1 += __shfl_xor_sync(0xffffffffu, rs1, 2);
        l0 = l0 * a0 + rs0;
        l1 = l1 * a1 + rs1;

#pragma unroll
        for (int dt = 0; dt < 16; dt++) {
            o[dt][0] *= a0; o[dt][1] *= a0;
            o[dt][2] *= a1; o[dt][3] *= a1;
        }

        // ---- PV: O += P V (3-term split) ----
#pragma unroll
        for (int ks = 0; ks < 4; ks++) {
            uint32_t ah[4] = { ph[2*ks][0], ph[2*ks][1], ph[2*ks+1][0], ph[2*ks+1][1] };
            uint32_t al[4] = { pl[2*ks][0], pl[2*ks][1], pl[2*ks+1][0], pl[2*ks+1][1] };
#pragma unroll
            for (int dt = 0; dt < 16; dt++) {
                const char* vb = sm + SM_VH + (dt * 8 + g) * ROWV + ks * 32 + tig * 4;
                uint32_t bhf[2], blf[2];
                bhf[0] = *(const uint32_t*)vb;
                bhf[1] = *(const uint32_t*)(vb + 16);
                blf[0] = *(const uint32_t*)(vb + 128 * ROWV);
                blf[1] = *(const uint32_t*)(vb + 128 * ROWV + 16);
                mma16816(o[dt], ah, bhf);
                mma16816(o[dt], ah, blf);
                mma16816(o[dt], al, bhf);
            }
        }
        __syncthreads();
    }

    // ---- epilogue: normalize, split, store to Xh/Xl [B,S,E] ----
    const float inv0 = 1.0f / l0;
    const float inv1 = 1.0f / l1;
    const int bI = bh >> 4;
    const int h  = bh & 15;
    const int row0 = q0 + wid * 16 + g;
#pragma unroll
    for (int dt = 0; dt < 16; dt++) {
        const int e = h * 128 + dt * 8 + 2 * tig;
        size_t adr0 = (size_t)(bI * SS + row0) * EE + e;
        size_t adr1 = adr0 + (size_t)8 * EE;
        uint32_t lo, hi;
        hi = pack_split(o[dt][0] * inv0, o[dt][1] * inv0, lo);
        *(uint32_t*)&Xh[adr0] = hi; *(uint32_t*)&Xl[adr0] = lo;
        hi = pack_split(o[dt][2] * inv1, o[dt][3] * inv1, lo);
        *(uint32_t*)&Xh[adr1] = hi; *(uint32_t*)&Xl[adr1] = lo;
    }
}

// ---------------------------------------------------------------------------
extern "C" void kernel_launch(void* const* d_in, const int* in_sizes, int n_in,
                              void* d_out, int out_size)
{
    const float* query  = (const float*)d_in[0];
    const float* key_in = (const float*)d_in[1];
    const float* value  = (const float*)d_in[2];
    const float* Wq = (const float*)d_in[3];
    const float* bq = (const float*)d_in[4];
    const float* Wk = (const float*)d_in[5];
    const float* bk = (const float*)d_in[6];
    const float* Wv = (const float*)d_in[7];
    const float* bv = (const float*)d_in[8];
    const float* Wo = (const float*)d_in[9];
    const float* bo = (const float*)d_in[10];
    float* out = (float*)d_out;

    __nv_bfloat16 *Qh, *Ql, *Kh, *Kl, *Vh, *Vl, *Xh, *Xl, *Wth, *Wtl;
    cudaGetSymbolAddress((void**)&Qh, g_Qh);
    cudaGetSymbolAddress((void**)&Ql, g_Ql);
    cudaGetSymbolAddress((void**)&Kh, g_Kh);
    cudaGetSymbolAddress((void**)&Kl, g_Kl);
    cudaGetSymbolAddress((void**)&Vh, g_Vh);
    cudaGetSymbolAddress((void**)&Vl, g_Vl);
    cudaGetSymbolAddress((void**)&Xh, g_Xh);
    cudaGetSymbolAddress((void**)&Xl, g_Xl);
    cudaGetSymbolAddress((void**)&Wth, g_Wth);
    cudaGetSymbolAddress((void**)&Wtl, g_Wtl);

    cudaFuncSetAttribute(gemm_mma_kernel<0>, cudaFuncAttributeMaxDynamicSharedMemorySize, GEMM_SMEM);
    cudaFuncSetAttribute(gemm_mma_kernel<1>, cudaFuncAttributeMaxDynamicSharedMemorySize, GEMM_SMEM);
    cudaFuncSetAttribute(gemm_mma_kernel<2>, cudaFuncAttributeMaxDynamicSharedMemorySize, GEMM_SMEM);
    cudaFuncSetAttribute(attn_mma_kernel, cudaFuncAttributeMaxDynamicSharedMemorySize, ATTN_SMEM);

    const int n4 = MROWS * EE / 4;
    dim3 gt(EE/32, EE/32), bt(32, 32);
    dim3 gg(EE/BN, MROWS/BM);

    // Q projection -> bf16 split head-major
    split_kernel<<<2048, 256>>>(query, Xh, Xl, n4);
    transpose_split_kernel<<<gt, bt>>>(Wq, Wth, Wtl);
    gemm_mma_kernel<1><<<gg, 256, GEMM_SMEM>>>(Xh, Xl, Wth, Wtl, bq, nullptr, Qh, Ql);
    // K projection
    split_kernel<<<2048, 256>>>(key_in, Xh, Xl, n4);
    transpose_split_kernel<<<gt, bt>>>(Wk, Wth, Wtl);
    gemm_mma_kernel<1><<<gg, 256, GEMM_SMEM>>>(Xh, Xl, Wth, Wtl, bk, nullptr, Kh, Kl);
    // V projection -> transposed [B*H, D, S]
    split_kernel<<<2048, 256>>>(value, Xh, Xl, n4);
    transpose_split_kernel<<<gt, bt>>>(Wv, Wth, Wtl);
    gemm_mma_kernel<2><<<gg, 256, GEMM_SMEM>>>(Xh, Xl, Wth, Wtl, bv, nullptr, Vh, Vl);

    // attention -> Xh/Xl
    dim3 ga(SS/AQT, BB*HH);     // (16, 32)
    attn_mma_kernel<<<ga, 256, ATTN_SMEM>>>(Qh, Ql, Kh, Kl, Vh, Vl, Xh, Xl);

    // output projection -> fp32 out
    transpose_split_kernel<<<gt, bt>>>(Wo, Wth, Wtl);
    gemm_mma_kernel<0><<<gg, 256, GEMM_SMEM>>>(Xh, Xl, Wth, Wtl, bo, out, nullptr, nullptr);
}